// round 6
// baseline (speedup 1.0000x reference)
#include <cuda_runtime.h>
#include <cstdint>

#define NC 10
#define D  64

__device__ float g_cc[NC * D];

__device__ __forceinline__ float sigmoidf_(float x) {
    return 1.0f / (1.0f + __expf(-x));
}

__device__ __forceinline__ void cp_async16(uint32_t smem_addr, const void* gptr) {
    asm volatile("cp.async.cg.shared.global [%0], [%1], 16;\n"
                 :: "r"(smem_addr), "l"(gptr));
}
__device__ __forceinline__ void cp_commit() {
    asm volatile("cp.async.commit_group;\n");
}
template <int N>
__device__ __forceinline__ void cp_wait() {
    asm volatile("cp.async.wait_group %0;\n" :: "n"(N));
}
__device__ __forceinline__ void l2_prefetch(const void* p) {
    asm volatile("prefetch.global.L2 [%0];" :: "l"(p));
}

// Bank-conflict-free weight tile layout: 64 rows, pitch 68 floats (17 quads).
// Logical quad v of row c lives at physical quad (v + 2c) & 15.
// Phase bank-group = (17c + p) mod 8 = (3c + v) mod 8 -> distinct per lane.

// =========================== CORE + PREFETCH KERNEL =========================
#define C_BUF   0          // 4 x 4352
#define C_CC    17408
#define C_K     18048
#define C_V     18688
#define C_TMP   19328
#define C_Q     19968
#define C_NEW   20608
#define C_GI    21248      // 10 x 192
#define C_GH    23168      // 10 x 192
#define C_H2    25088      // 10 x 128
#define C_ATTN  26368      // 100
#define C_MEAN  26468
#define C_RSTD  26480
#define C_P1    26496      // 20
#define C_P2    26516      // 20
#define C_PA    26536      // 320
#define C_PB    26856      // 320
#define CORE_DYN_BYTES (27200 * 4)

__global__ void __launch_bounds__(640, 1)
slot_iter_kernel(
    const float* __restrict__ cc0,
    const float* __restrict__ Wk, const float* __restrict__ bk,
    const float* __restrict__ Wq, const float* __restrict__ bq,
    const float* __restrict__ Wv, const float* __restrict__ bv,
    const float* __restrict__ cc_g, const float* __restrict__ cc_b,
    const float* __restrict__ W_ih, const float* __restrict__ W_hh,
    const float* __restrict__ b_ih, const float* __restrict__ b_hh,
    const float* __restrict__ ln_g, const float* __restrict__ ln_b,
    const float* __restrict__ W1, const float* __restrict__ b1,
    const float* __restrict__ W2, const float* __restrict__ b2,
    const float* __restrict__ Wa, const float* __restrict__ Wb)
{
    extern __shared__ float dyn[];
    const int tid = threadIdx.x;

    if (blockIdx.x != 0) {
        // L2 warm for the MLP kernel (runs concurrently with block 0's core)
        const int nlines = 4096 * 128;       // per matrix
        const int gt = (blockIdx.x - 1) * 640 + tid;
        const int stride = 147 * 640;
        const char* pa = (const char*)Wa;
        const char* pb = (const char*)Wb;
        for (int idx = gt; idx < nlines; idx += stride) {
            l2_prefetch(pa + (size_t)idx * 128);
            l2_prefetch(pb + (size_t)idx * 128);
        }
        return;
    }

    const int warp = tid >> 5, lane = tid & 31;
    const int nn_  = tid >> 6, ii = tid & 63;   // state-op layout
    const int c = tid & 63, g = tid >> 6;       // gemm layout
    const int h = g & 1, p = g >> 1;
    const int n0 = 2 * p, n1 = 2 * p + 1;

    int tcount = 0;

    // stream one 64x64 tile with swizzled quad placement
    auto issue_tile = [&](int slot, const float* src, int st) {
        uint32_t sb = (uint32_t)__cvta_generic_to_shared(dyn + C_BUF + slot * 4352);
        #pragma unroll
        for (int rep = 0; rep < 2; rep++) {
            int ch = tid + rep * 640;
            if (ch < 1024) {
                int r = ch >> 4, qv = ch & 15;
                cp_async16(sb + r * 272 + ((qv + 2 * r) & 15) * 16,
                           (const char*)src + (size_t)(r * st + qv * 4) * 4);
            }
        }
    };

    auto tile_src = [&](int t, const float*& ptr, int& st) {
        ptr = nullptr; st = 64;
        if (t == 0) { ptr = Wk; return; }
        if (t == 1) { ptr = Wv; return; }
        if (t >= 35) return;
        switch ((t - 2) % 11) {
            case 0:  ptr = Wq; break;
            case 1:  ptr = W_ih; break;
            case 2:  ptr = W_ih + 64 * 64; break;
            case 3:  ptr = W_ih + 128 * 64; break;
            case 4:  ptr = W_hh; break;
            case 5:  ptr = W_hh + 64 * 64; break;
            case 6:  ptr = W_hh + 128 * 64; break;
            case 7:  ptr = W1; break;
            case 8:  ptr = W1 + 64 * 64; break;
            case 9:  ptr = W2;      st = 128; break;
            case 10: ptr = W2 + 64; st = 128; break;
        }
    };

    auto tile_begin = [&]() { cp_wait<2>(); __syncthreads(); };
    auto tile_end = [&]() {
        const float* ptr; int st;
        tile_src(tcount + 3, ptr, st);
        if (ptr) { issue_tile((tcount + 3) & 3, ptr, st); }
        cp_commit();
        tcount++;
    };

    // mode: 0 = bias, 1 = bias+relu, 2 = final (acc + qbuf + neww -> cc)
    auto gemm = [&](const float* act, int apitch,
                    const float* bias, int boff,
                    float* outp, int opitch, int ooff, int mode) {
        const float* wrow = dyn + C_BUF + (tcount & 3) * 4352 + c * 68;
        const float4* a0 = (const float4*)(act + n0 * apitch + h * 32);
        const float4* a1 = (const float4*)(act + n1 * apitch + h * 32);
        float acc0 = 0.f, acc1 = 0.f;
        #pragma unroll
        for (int j4 = 0; j4 < 8; j4++) {
            int v = h * 8 + j4;
            float4 wv = *(const float4*)(wrow + ((v + 2 * c) & 15) * 4);
            float4 x0 = a0[j4];
            float4 x1 = a1[j4];
            acc0 = fmaf(wv.x, x0.x, acc0); acc1 = fmaf(wv.x, x1.x, acc1);
            acc0 = fmaf(wv.y, x0.y, acc0); acc1 = fmaf(wv.y, x1.y, acc1);
            acc0 = fmaf(wv.z, x0.z, acc0); acc1 = fmaf(wv.z, x1.z, acc1);
            acc0 = fmaf(wv.w, x0.w, acc0); acc1 = fmaf(wv.w, x1.w, acc1);
        }
        if (h == 1) {
            dyn[C_PA + p * 64 + c] = acc0;
            dyn[C_PB + p * 64 + c] = acc1;
        }
        __syncthreads();
        if (h == 0) {
            float r0 = acc0 + dyn[C_PA + p * 64 + c];
            float r1 = acc1 + dyn[C_PB + p * 64 + c];
            if (mode == 2) {
                r0 += dyn[C_Q + n0 * 64 + c] + dyn[C_NEW + n0 * 64 + c];
                r1 += dyn[C_Q + n1 * 64 + c] + dyn[C_NEW + n1 * 64 + c];
            } else {
                float b = __ldg(bias + boff + c);
                r0 += b; r1 += b;
                if (mode == 1) { r0 = fmaxf(r0, 0.f); r1 = fmaxf(r1, 0.f); }
            }
            outp[n0 * opitch + ooff + c] = r0;
            outp[n1 * opitch + ooff + c] = r1;
        }
    };

    auto layernorm = [&](const float* src, const float* gg, const float* bb_,
                         float* dst) {
        float x = src[nn_ * 64 + ii];
        float s = x, s2 = x * x;
        #pragma unroll
        for (int o = 16; o; o >>= 1) {
            s  += __shfl_down_sync(0xffffffffu, s,  o);
            s2 += __shfl_down_sync(0xffffffffu, s2, o);
        }
        if (lane == 0) { dyn[C_P1 + warp] = s; dyn[C_P2 + warp] = s2; }
        __syncthreads();
        if (tid < NC) {
            float ss  = dyn[C_P1 + 2 * tid] + dyn[C_P1 + 2 * tid + 1];
            float ss2 = dyn[C_P2 + 2 * tid] + dyn[C_P2 + 2 * tid + 1];
            float m = ss * (1.0f / D);
            float var = ss2 * (1.0f / D) - m * m;
            dyn[C_MEAN + tid] = m;
            dyn[C_RSTD + tid] = rsqrtf(var + 1e-5f);
        }
        __syncthreads();
        dst[nn_ * 64 + ii] = (src[nn_ * 64 + ii] - dyn[C_MEAN + nn_]) * dyn[C_RSTD + nn_]
                             * __ldg(gg + ii) + __ldg(bb_ + ii);
    };

    {   // prologue: tiles 0..2
        const float* ptr; int st;
        tile_src(0, ptr, st); issue_tile(0, ptr, st); cp_commit();
        tile_src(1, ptr, st); issue_tile(1, ptr, st); cp_commit();
        tile_src(2, ptr, st); issue_tile(2, ptr, st); cp_commit();
    }
    dyn[C_CC + tid] = cc0[tid];

    tile_begin(); gemm(dyn + C_CC, 64, bk, 0, dyn + C_K, 64, 0, 0); tile_end();
    tile_begin(); gemm(dyn + C_CC, 64, bv, 0, dyn + C_V, 64, 0, 0); tile_end();

    for (int it = 0; it < 3; it++) {
        __syncthreads();
        layernorm(dyn + C_CC, cc_g, cc_b, dyn + C_TMP);

        tile_begin(); gemm(dyn + C_TMP, 64, bq, 0, dyn + C_Q, 64, 0, 0); tile_end();
        __syncthreads();

        if (tid < NC * NC) {
            int an = tid / NC, am = tid % NC;
            float a = 0.f;
            #pragma unroll 8
            for (int j = 0; j < D; j++)
                a = fmaf(dyn[C_K + an * 64 + j], dyn[C_Q + am * 64 + j], a);
            dyn[C_ATTN + an * NC + am] = a * 0.125f;
        }
        __syncthreads();
        if (tid < NC) {   // softmax over axis 0
            int m = tid;
            float mx = dyn[C_ATTN + m];
            #pragma unroll
            for (int r = 1; r < NC; r++) mx = fmaxf(mx, dyn[C_ATTN + r * NC + m]);
            float e[NC], sum = 0.f;
            #pragma unroll
            for (int r = 0; r < NC; r++) {
                e[r] = __expf(dyn[C_ATTN + r * NC + m] - mx); sum += e[r];
            }
            float inv = 1.0f / sum;
            #pragma unroll
            for (int r = 0; r < NC; r++) dyn[C_ATTN + r * NC + m] = e[r] * inv + 1e-8f;
        }
        __syncthreads();
        if (tid < NC) {   // row renorm
            float sum = 0.f;
            #pragma unroll
            for (int m = 0; m < NC; m++) sum += dyn[C_ATTN + tid * NC + m];
            float inv = 1.0f / sum;
            #pragma unroll
            for (int m = 0; m < NC; m++) dyn[C_ATTN + tid * NC + m] *= inv;
        }
        __syncthreads();
        {   // updates = attn @ v
            float u = 0.f;
            #pragma unroll
            for (int m = 0; m < NC; m++)
                u = fmaf(dyn[C_ATTN + nn_ * NC + m], dyn[C_V + m * 64 + ii], u);
            dyn[C_TMP + nn_ * 64 + ii] = u;
        }

        tile_begin(); gemm(dyn + C_TMP, 64, b_ih, 0,   dyn + C_GI, 192, 0,   0); tile_end();
        tile_begin(); gemm(dyn + C_TMP, 64, b_ih, 64,  dyn + C_GI, 192, 64,  0); tile_end();
        tile_begin(); gemm(dyn + C_TMP, 64, b_ih, 128, dyn + C_GI, 192, 128, 0); tile_end();
        tile_begin(); gemm(dyn + C_CC,  64, b_hh, 0,   dyn + C_GH, 192, 0,   0); tile_end();
        tile_begin(); gemm(dyn + C_CC,  64, b_hh, 64,  dyn + C_GH, 192, 64,  0); tile_end();
        tile_begin(); gemm(dyn + C_CC,  64, b_hh, 128, dyn + C_GH, 192, 128, 0); tile_end();
        __syncthreads();

        {   // GRU elementwise -> s_new
            float gi_r = dyn[C_GI + nn_ * 192 + ii],       gh_r = dyn[C_GH + nn_ * 192 + ii];
            float gi_z = dyn[C_GI + nn_ * 192 + 64 + ii],  gh_z = dyn[C_GH + nn_ * 192 + 64 + ii];
            float gi_n = dyn[C_GI + nn_ * 192 + 128 + ii], gh_n = dyn[C_GH + nn_ * 192 + 128 + ii];
            float r = sigmoidf_(gi_r + gh_r);
            float z = sigmoidf_(gi_z + gh_z);
            float nv = tanhf(gi_n + r * gh_n);
            dyn[C_NEW + nn_ * 64 + ii] = (1.0f - z) * nv + z * dyn[C_CC + nn_ * 64 + ii];
        }
        __syncthreads();

        layernorm(dyn + C_NEW, ln_g, ln_b, dyn + C_TMP);

        tile_begin(); gemm(dyn + C_TMP, 64, b1, 0,  dyn + C_H2, 128, 0,  1); tile_end();
        tile_begin(); gemm(dyn + C_TMP, 64, b1, 64, dyn + C_H2, 128, 64, 1); tile_end();

        tile_begin(); gemm(dyn + C_H2, 128, b2, 0, dyn + C_Q, 64, 0, 0); tile_end();
        tile_begin(); gemm(dyn + C_H2 + 64, 128, b2, 0, dyn + C_CC, 64, 0, 2); tile_end();
    }
    __syncthreads();
    g_cc[tid] = dyn[C_CC + tid];
}

// =========================== PERSISTENT MLP KERNEL ==========================
// 296 blocks (2/SM) x 256 threads; each block owns a 14-slot chain.
// Ring of 4 swizzled weight buffers; slot k's compute overlaps slot k+1's
// cp.async weight stream -> DRAM never idles.
// Thread layout: c = tid&63 (output feature), q = tid>>6 (j-quarter of 16).
#define NBLK  296
#define ITERS 14
#define M_RING 0           // 4 x 4352
#define M_CC   17408       // 640
#define M_HS   18048       // 640
#define M_PART 18688       // 3 x 640
#define MLP_DYN_BYTES (20608 * 4)

__global__ void __launch_bounds__(256, 2)
slot_mlp_kernel(
    const float* __restrict__ Wa, const float* __restrict__ ba,
    const float* __restrict__ Wb, const float* __restrict__ bb,
    float* __restrict__ out)
{
    extern __shared__ float sm[];
    const int tid = threadIdx.x;
    const int c = tid & 63, q = tid >> 6;

    // stream one 64x64 weight matrix into ring buffer bufi (swizzled)
    auto issue = [&](int bufi, const float* gsrc) {
        uint32_t sb = (uint32_t)__cvta_generic_to_shared(sm + M_RING + bufi * 4352);
        #pragma unroll
        for (int rep = 0; rep < 4; rep++) {
            int ch = tid + rep * 256;
            int r = ch >> 4, qv = ch & 15;
            cp_async16(sb + r * 272 + ((qv + 2 * r) & 15) * 16,
                       (const char*)gsrc + ch * 16);
        }
    };

    // prologue: Wa(k0), Wb(k0), Wa(k1), Wb(k1)
    {
        int s0 = blockIdx.x, s1 = blockIdx.x + NBLK;
        issue(0, Wa + (size_t)s0 * (D * D)); cp_commit();
        issue(1, Wb + (size_t)s0 * (D * D)); cp_commit();
        issue(2, Wa + (size_t)s1 * (D * D)); cp_commit();
        issue(3, Wb + (size_t)s1 * (D * D)); cp_commit();
    }

    for (int t = tid; t < NC * D; t += 256)
        sm[M_CC + t] = g_cc[t];

    float acc[NC];

    for (int k = 0; k < ITERS; k++) {
        const int slot  = blockIdx.x + k * NBLK;
        const bool valid = slot < 4096;
        const int slot2 = blockIdx.x + (k + 2) * NBLK;
        const int bufA = (2 * k) & 3, bufB = (2 * k + 1) & 3;

        cp_wait<3>();          // Wa(k) ready
        __syncthreads();

        // ---- Stage 1 partials ----
        if (valid) {
            const float* wrow = sm + M_RING + bufA * 4352 + c * 68;
            #pragma unroll
            for (int n = 0; n < NC; n++) acc[n] = 0.f;
            #pragma unroll
            for (int t = 0; t < 4; t++) {
                int v = q * 4 + t;
                float4 wv = *(const float4*)(wrow + ((v + 2 * c) & 15) * 4);
                #pragma unroll
                for (int n = 0; n < NC; n++) {
                    float4 x = *(const float4*)&sm[M_CC + n * 64 + v * 4];
                    acc[n] = fmaf(wv.x, x.x, acc[n]);
                    acc[n] = fmaf(wv.y, x.y, acc[n]);
                    acc[n] = fmaf(wv.z, x.z, acc[n]);
                    acc[n] = fmaf(wv.w, x.w, acc[n]);
                }
            }
            if (q) {
                #pragma unroll
                for (int n = 0; n < NC; n++)
                    sm[M_PART + (q - 1) * 640 + n * 64 + c] = acc[n];
            }
        }
        __syncthreads();
        if (valid && q == 0) {
            float bias = __ldg(ba + slot * D + c);
            #pragma unroll
            for (int n = 0; n < NC; n++) {
                float s = acc[n] + sm[M_PART + n * 64 + c]
                        + sm[M_PART + 640 + n * 64 + c]
                        + sm[M_PART + 1280 + n * 64 + c] + bias;
                sm[M_HS + n * 64 + c] = fmaxf(s, 0.f);
            }
        }

        cp_wait<2>();          // Wb(k) ready; bufA reads finished (sync above)
        __syncthreads();

        if (slot2 < 4096) issue(bufA, Wa + (size_t)slot2 * (D * D));
        cp_commit();

        // ---- Stage 2 partials + max ----
        if (valid) {
            const float* wrow = sm + M_RING + bufB * 4352 + c * 68;
            #pragma unroll
            for (int n = 0; n < NC; n++) acc[n] = 0.f;
            #pragma unroll
            for (int t = 0; t < 4; t++) {
                int v = q * 4 + t;
                float4 wv = *(const float4*)(wrow + ((v + 2 * c) & 15) * 4);
                #pragma unroll
                for (int n = 0; n < NC; n++) {
                    float4 x = *(const float4*)&sm[M_HS + n * 64 + v * 4];
                    acc[n] = fmaf(wv.x, x.x, acc[n]);
                    acc[n] = fmaf(wv.y, x.y, acc[n]);
                    acc[n] = fmaf(wv.z, x.z, acc[n]);
                    acc[n] = fmaf(wv.w, x.w, acc[n]);
                }
            }
            if (q) {
                #pragma unroll
                for (int n = 0; n < NC; n++)
                    sm[M_PART + (q - 1) * 640 + n * 64 + c] = acc[n];
            }
        }
        __syncthreads();       // bufB reads finished
        if (valid && q == 0) {
            float bias = __ldg(bb + slot * D + c);
            float m = -3.4e38f;
            #pragma unroll
            for (int n = 0; n < NC; n++) {
                float s = acc[n] + sm[M_PART + n * 64 + c]
                        + sm[M_PART + 640 + n * 64 + c]
                        + sm[M_PART + 1280 + n * 64 + c] + bias;
                m = fmaxf(m, s);
            }
            out[slot * D + c] = m;
        }

        if (slot2 < 4096) issue(bufB, Wb + (size_t)slot2 * (D * D));
        cp_commit();
    }
}

// ---------------------------------------------------------------------------
extern "C" void kernel_launch(void* const* d_in, const int* in_sizes, int n_in,
                              void* d_out, int out_size)
{
    const float* cc0  = (const float*)d_in[0];
    const float* Wk   = (const float*)d_in[1];
    const float* bk   = (const float*)d_in[2];
    const float* Wq   = (const float*)d_in[3];
    const float* bq   = (const float*)d_in[4];
    const float* Wv   = (const float*)d_in[5];
    const float* bv   = (const float*)d_in[6];
    const float* cc_g = (const float*)d_in[7];
    const float* cc_b = (const float*)d_in[8];
    const float* W_ih = (const float*)d_in[9];
    const float* W_hh = (const float*)d_in[10];
    const float* b_ih = (const float*)d_in[11];
    const float* b_hh = (const float*)d_in[12];
    const float* ln_g = (const float*)d_in[13];
    const float* ln_b = (const float*)d_in[14];
    const float* W1   = (const float*)d_in[15];
    const float* b1   = (const float*)d_in[16];
    const float* W2   = (const float*)d_in[17];
    const float* b2   = (const float*)d_in[18];
    const float* Wa   = (const float*)d_in[19];
    const float* ba   = (const float*)d_in[20];
    const float* Wb   = (const float*)d_in[21];
    const float* bb   = (const float*)d_in[22];

    cudaFuncSetAttribute(slot_iter_kernel,
                         cudaFuncAttributeMaxDynamicSharedMemorySize, CORE_DYN_BYTES);
    cudaFuncSetAttribute(slot_mlp_kernel,
                         cudaFuncAttributeMaxDynamicSharedMemorySize, MLP_DYN_BYTES);

    slot_iter_kernel<<<148, 640, CORE_DYN_BYTES>>>(
        cc0, Wk, bk, Wq, bq, Wv, bv, cc_g, cc_b,
        W_ih, W_hh, b_ih, b_hh, ln_g, ln_b, W1, b1, W2, b2, Wa, Wb);
    slot_mlp_kernel<<<NBLK, 256, MLP_DYN_BYTES>>>(Wa, ba, Wb, bb, (float*)d_out);
}

// round 9
// speedup vs baseline: 1.0300x; 1.0300x over previous
#include <cuda_runtime.h>
#include <cstdint>

#define NC 10
#define D  64
#define NBLK 296

__device__ float g_cc[NC * D];
__device__ int   g_ctr;

__device__ __forceinline__ float sigmoidf_(float x) {
    return 1.0f / (1.0f + __expf(-x));
}
__device__ __forceinline__ void cp_async16(uint32_t smem_addr, const void* gptr) {
    asm volatile("cp.async.cg.shared.global [%0], [%1], 16;\n"
                 :: "r"(smem_addr), "l"(gptr));
}
__device__ __forceinline__ void cp_commit() {
    asm volatile("cp.async.commit_group;\n");
}
template <int N>
__device__ __forceinline__ void cp_wait() {
    asm volatile("cp.async.wait_group %0;\n" :: "n"(N));
}
__device__ __forceinline__ void l2_prefetch(const void* p) {
    asm volatile("prefetch.global.L2 [%0];" :: "l"(p));
}
__device__ __forceinline__ void ffma2(unsigned long long& acc,
                                      unsigned long long a, unsigned long long b) {
    asm("fma.rn.f32x2 %0, %1, %2, %0;" : "+l"(acc) : "l"(a), "l"(b));
}
__device__ __forceinline__ float unpack_add(unsigned long long acc) {
    float lo, hi;
    asm("mov.b64 {%0, %1}, %2;" : "=f"(lo), "=f"(hi) : "l"(acc));
    return lo + hi;
}

__global__ void reset_kernel() { g_ctr = 0; }

// =========================== CORE KERNEL (grid=1) ===========================
// 640 threads. Ring-3 cp.async tile streaming (prefetch depth 2).
// GEMM: c = tid&63 (out col), g = tid>>6; g<8 compute j-floats [8g,8g+8) for
// ALL 10 n (weights read once), partials in smem, 640-thread reduction.
// smem (floats):
#define C_BUF   0          // 3 x 4352
#define C_CC    13056
#define C_K     13696
#define C_V     14336
#define C_TMP   14976
#define C_Q     15616
#define C_NEW   16256
#define C_GI    16896      // 10 x 192
#define C_GH    18816      // 10 x 192
#define C_H2    20736      // 10 x 128
#define C_ATTN  22016      // 100
#define C_MEAN  22116
#define C_RSTD  22126
#define C_P1    22136      // 20
#define C_P2    22156      // 20
#define C_PART  22176      // 8 x 640
#define CORE_DYN_BYTES (27296 * 4)

__global__ void __launch_bounds__(640, 1)
slot_iter_kernel(
    const float* __restrict__ cc0,
    const float* __restrict__ Wk, const float* __restrict__ bk,
    const float* __restrict__ Wq, const float* __restrict__ bq,
    const float* __restrict__ Wv, const float* __restrict__ bv,
    const float* __restrict__ cc_g, const float* __restrict__ cc_b,
    const float* __restrict__ W_ih, const float* __restrict__ W_hh,
    const float* __restrict__ b_ih, const float* __restrict__ b_hh,
    const float* __restrict__ ln_g, const float* __restrict__ ln_b,
    const float* __restrict__ W1, const float* __restrict__ b1,
    const float* __restrict__ W2, const float* __restrict__ b2)
{
#if __CUDA_ARCH__ >= 900
    cudaTriggerProgrammaticLaunchCompletion();   // let the MLP kernel start streaming
#endif
    extern __shared__ float dyn[];
    const int tid  = threadIdx.x;
    const int warp = tid >> 5, lane = tid & 31;
    const int nn_  = tid >> 6, ii = tid & 63;
    const int c = tid & 63, g = tid >> 6;

    int tcount = 0;

    auto issue_tile = [&](int slot, const float* src, int st) {
        uint32_t sb = (uint32_t)__cvta_generic_to_shared(dyn + C_BUF + slot * 4352);
        #pragma unroll
        for (int rep = 0; rep < 2; rep++) {
            int ch = tid + rep * 640;
            if (ch < 1024) {
                int r = ch >> 4, qv = ch & 15;
                cp_async16(sb + r * 272 + qv * 16,
                           (const char*)src + (size_t)(r * st + qv * 4) * 4);
            }
        }
    };

    auto tile_src = [&](int t, const float*& ptr, int& st) {
        ptr = nullptr; st = 64;
        if (t == 0) { ptr = Wk; return; }
        if (t == 1) { ptr = Wv; return; }
        if (t >= 35) return;
        switch ((t - 2) % 11) {
            case 0:  ptr = Wq; break;
            case 1:  ptr = W_ih; break;
            case 2:  ptr = W_ih + 64 * 64; break;
            case 3:  ptr = W_ih + 128 * 64; break;
            case 4:  ptr = W_hh; break;
            case 5:  ptr = W_hh + 64 * 64; break;
            case 6:  ptr = W_hh + 128 * 64; break;
            case 7:  ptr = W1; break;
            case 8:  ptr = W1 + 64 * 64; break;
            case 9:  ptr = W2;      st = 128; break;
            case 10: ptr = W2 + 64; st = 128; break;
        }
    };

    auto tile_begin = [&]() { cp_wait<1>(); __syncthreads(); };
    auto tile_end = [&]() {
        const float* ptr; int st;
        tile_src(tcount + 2, ptr, st);
        if (ptr) issue_tile((tcount + 2) % 3, ptr, st);
        cp_commit();
        tcount++;
    };

    // mode: 0 = bias, 1 = bias+relu, 2 = final (sum + C_Q + C_NEW -> out)
    auto gemm = [&](const float* act, int apitch,
                    const float* bias, int boff,
                    float* outp, int opitch, int ooff, int mode) {
        if (g < 8) {
            const float* wbase = dyn + C_BUF + (tcount % 3) * 4352 + c * 68 + g * 8;
            ulonglong2 w0 = *(const ulonglong2*)(wbase);
            ulonglong2 w1 = *(const ulonglong2*)(wbase + 4);
            #pragma unroll
            for (int n = 0; n < NC; n++) {
                const float* ab = act + n * apitch + g * 8;
                ulonglong2 x0 = *(const ulonglong2*)(ab);
                ulonglong2 x1 = *(const ulonglong2*)(ab + 4);
                unsigned long long acc = 0ULL;
                ffma2(acc, w0.x, x0.x); ffma2(acc, w0.y, x0.y);
                ffma2(acc, w1.x, x1.x); ffma2(acc, w1.y, x1.y);
                dyn[C_PART + g * 640 + n * 64 + c] = unpack_add(acc);
            }
        }
        __syncthreads();
        float s = 0.f;
        #pragma unroll
        for (int gg = 0; gg < 8; gg++)
            s += dyn[C_PART + gg * 640 + nn_ * 64 + ii];
        if (mode == 2) {
            s += dyn[C_Q + nn_ * 64 + ii] + dyn[C_NEW + nn_ * 64 + ii];
        } else {
            s += __ldg(bias + boff + ii);
            if (mode == 1) s = fmaxf(s, 0.f);
        }
        outp[nn_ * opitch + ooff + ii] = s;
    };

    auto layernorm = [&](const float* src, const float* gg, const float* bb_,
                         float* dst) {
        float x = src[nn_ * 64 + ii];
        float s = x, s2 = x * x;
        #pragma unroll
        for (int o = 16; o; o >>= 1) {
            s  += __shfl_down_sync(0xffffffffu, s,  o);
            s2 += __shfl_down_sync(0xffffffffu, s2, o);
        }
        if (lane == 0) { dyn[C_P1 + warp] = s; dyn[C_P2 + warp] = s2; }
        __syncthreads();
        if (tid < NC) {
            float ss  = dyn[C_P1 + 2 * tid] + dyn[C_P1 + 2 * tid + 1];
            float ss2 = dyn[C_P2 + 2 * tid] + dyn[C_P2 + 2 * tid + 1];
            float m = ss * (1.0f / D);
            float var = ss2 * (1.0f / D) - m * m;
            dyn[C_MEAN + tid] = m;
            dyn[C_RSTD + tid] = rsqrtf(var + 1e-5f);
        }
        __syncthreads();
        dst[nn_ * 64 + ii] = (src[nn_ * 64 + ii] - dyn[C_MEAN + nn_]) * dyn[C_RSTD + nn_]
                             * __ldg(gg + ii) + __ldg(bb_ + ii);
    };

    {   // prologue: tiles 0, 1
        const float* ptr; int st;
        tile_src(0, ptr, st); issue_tile(0, ptr, st); cp_commit();
        tile_src(1, ptr, st); issue_tile(1, ptr, st); cp_commit();
    }
    dyn[C_CC + tid] = cc0[tid];

    tile_begin(); gemm(dyn + C_CC, 64, bk, 0, dyn + C_K, 64, 0, 0); tile_end();
    tile_begin(); gemm(dyn + C_CC, 64, bv, 0, dyn + C_V, 64, 0, 0); tile_end();

    for (int it = 0; it < 3; it++) {
        __syncthreads();
        layernorm(dyn + C_CC, cc_g, cc_b, dyn + C_TMP);

        tile_begin(); gemm(dyn + C_TMP, 64, bq, 0, dyn + C_Q, 64, 0, 0); tile_end();
        __syncthreads();

        if (tid < NC * NC) {
            int an = tid / NC, am = tid % NC;
            float a = 0.f;
            #pragma unroll 8
            for (int j = 0; j < D; j++)
                a = fmaf(dyn[C_K + an * 64 + j], dyn[C_Q + am * 64 + j], a);
            dyn[C_ATTN + an * NC + am] = a * 0.125f;
        }
        __syncthreads();
        if (tid < NC) {   // softmax over axis 0 (column m)
            int m = tid;
            float mx = dyn[C_ATTN + m];
            #pragma unroll
            for (int r = 1; r < NC; r++) mx = fmaxf(mx, dyn[C_ATTN + r * NC + m]);
            float e[NC], sum = 0.f;
            #pragma unroll
            for (int r = 0; r < NC; r++) {
                e[r] = __expf(dyn[C_ATTN + r * NC + m] - mx); sum += e[r];
            }
            float inv = 1.0f / sum;
            #pragma unroll
            for (int r = 0; r < NC; r++) dyn[C_ATTN + r * NC + m] = e[r] * inv + 1e-8f;
        }
        __syncthreads();
        if (tid < NC) {   // row renorm
            float sum = 0.f;
            #pragma unroll
            for (int m = 0; m < NC; m++) sum += dyn[C_ATTN + tid * NC + m];
            float inv = 1.0f / sum;
            #pragma unroll
            for (int m = 0; m < NC; m++) dyn[C_ATTN + tid * NC + m] *= inv;
        }
        __syncthreads();
        {   // updates = attn @ v
            float u = 0.f;
            #pragma unroll
            for (int m = 0; m < NC; m++)
                u = fmaf(dyn[C_ATTN + nn_ * NC + m], dyn[C_V + m * 64 + ii], u);
            dyn[C_TMP + nn_ * 64 + ii] = u;
        }

        tile_begin(); gemm(dyn + C_TMP, 64, b_ih, 0,   dyn + C_GI, 192, 0,   0); tile_end();
        tile_begin(); gemm(dyn + C_TMP, 64, b_ih, 64,  dyn + C_GI, 192, 64,  0); tile_end();
        tile_begin(); gemm(dyn + C_TMP, 64, b_ih, 128, dyn + C_GI, 192, 128, 0); tile_end();
        tile_begin(); gemm(dyn + C_CC,  64, b_hh, 0,   dyn + C_GH, 192, 0,   0); tile_end();
        tile_begin(); gemm(dyn + C_CC,  64, b_hh, 64,  dyn + C_GH, 192, 64,  0); tile_end();
        tile_begin(); gemm(dyn + C_CC,  64, b_hh, 128, dyn + C_GH, 192, 128, 0); tile_end();
        __syncthreads();

        {   // GRU elementwise -> s_new
            float gi_r = dyn[C_GI + nn_ * 192 + ii],       gh_r = dyn[C_GH + nn_ * 192 + ii];
            float gi_z = dyn[C_GI + nn_ * 192 + 64 + ii],  gh_z = dyn[C_GH + nn_ * 192 + 64 + ii];
            float gi_n = dyn[C_GI + nn_ * 192 + 128 + ii], gh_n = dyn[C_GH + nn_ * 192 + 128 + ii];
            float r = sigmoidf_(gi_r + gh_r);
            float z = sigmoidf_(gi_z + gh_z);
            float nv = tanhf(gi_n + r * gh_n);
            dyn[C_NEW + nn_ * 64 + ii] = (1.0f - z) * nv + z * dyn[C_CC + nn_ * 64 + ii];
        }
        __syncthreads();

        layernorm(dyn + C_NEW, ln_g, ln_b, dyn + C_TMP);

        tile_begin(); gemm(dyn + C_TMP, 64, b1, 0,  dyn + C_H2, 128, 0,  1); tile_end();
        tile_begin(); gemm(dyn + C_TMP, 64, b1, 64, dyn + C_H2, 128, 64, 1); tile_end();

        tile_begin(); gemm(dyn + C_H2, 128, b2, 0, dyn + C_Q, 64, 0, 0); tile_end();
        tile_begin(); gemm(dyn + C_H2 + 64, 128, b2, 0, dyn + C_CC, 64, 0, 2); tile_end();
    }
    __syncthreads();
    g_cc[tid] = dyn[C_CC + tid];
}

// ==================== PERSISTENT WORK-STEALING MLP (PDL) ====================
// 296 blocks x 256 threads, ring-4 weight buffers, atomic slot counter.
// Launched with programmatic stream serialization: streams + L2-prefetches
// ALL weights while the core runs; gridsync only before touching g_cc.
// Thread layout: c = tid&63 (out feature), q = tid>>6 (j-quarter).
#define M_RING 0           // 4 x 4352
#define M_CC   17408       // 640
#define M_HS   18048       // 640
#define M_PART 18688       // 3 x 640
#define M_SLT  20608       // 4 ints
#define MLP_DYN_BYTES (20616 * 4)

__global__ void __launch_bounds__(256, 2)
slot_mlp_kernel(
    const float* __restrict__ Wa, const float* __restrict__ ba,
    const float* __restrict__ Wb, const float* __restrict__ bb,
    float* __restrict__ out)
{
    extern __shared__ float sm[];
    int* slt = (int*)&sm[M_SLT];
    const int tid = threadIdx.x;
    const int c = tid & 63, q = tid >> 6;

    auto issue = [&](int bufi, const float* gsrc) {
        uint32_t sb = (uint32_t)__cvta_generic_to_shared(sm + M_RING + bufi * 4352);
        #pragma unroll
        for (int rep = 0; rep < 4; rep++) {
            int ch = tid + rep * 256;
            int r = ch >> 4, qv = ch & 15;
            cp_async16(sb + r * 272 + qv * 16, (const char*)gsrc + ch * 16);
        }
    };

    // grab first two slots
    if (tid == 0) {
        slt[0] = atomicAdd(&g_ctr, 1);
        slt[1] = atomicAdd(&g_ctr, 1);
    }
    __syncthreads();
    int s0 = slt[0], s1 = slt[1];

    if (s0 < 4096) issue(0, Wa + (size_t)s0 * 4096);
    cp_commit();
    if (s0 < 4096) issue(1, Wb + (size_t)s0 * 4096);
    cp_commit();
    if (s1 < 4096) issue(2, Wa + (size_t)s1 * 4096);
    cp_commit();
    if (s1 < 4096) issue(3, Wb + (size_t)s1 * 4096);
    cp_commit();

    // L2-prefetch the whole weight stream (overlaps the core via PDL)
    {
        const int nlines = 4096 * 128;
        int gt = blockIdx.x * 256 + tid;
        const int stride = NBLK * 256;
        for (int idx = gt; idx < nlines; idx += stride) {
            l2_prefetch((const char*)Wa + (size_t)idx * 128);
            l2_prefetch((const char*)Wb + (size_t)idx * 128);
        }
    }

#if __CUDA_ARCH__ >= 900
    cudaGridDependencySynchronize();    // wait for the core's g_cc
#endif

    for (int t0 = tid; t0 < NC * D; t0 += 256)
        sm[M_CC + t0] = g_cc[t0];

    int t = 0;
    while (s0 < 4096) {
        const int bufA = (2 * t) & 3, bufB = (2 * t + 1) & 3;

        if (tid == 0) slt[2] = atomicAdd(&g_ctr, 1);
        cp_wait<3>();
        __syncthreads();                 // Wa(s0) ready; cc & slt[2] visible
        const int s2 = slt[2];

        float accs[NC];
        // ---- stage 1: weights bufA, acts = cc ----
        {
            const float* wbase = sm + M_RING + bufA * 4352 + c * 68 + q * 16;
            ulonglong2 w0 = *(const ulonglong2*)(wbase);
            ulonglong2 w1 = *(const ulonglong2*)(wbase + 4);
            ulonglong2 w2 = *(const ulonglong2*)(wbase + 8);
            ulonglong2 w3 = *(const ulonglong2*)(wbase + 12);
            #pragma unroll
            for (int n = 0; n < NC; n++) {
                const float* ab = sm + M_CC + n * 64 + q * 16;
                ulonglong2 x0 = *(const ulonglong2*)(ab);
                ulonglong2 x1 = *(const ulonglong2*)(ab + 4);
                ulonglong2 x2 = *(const ulonglong2*)(ab + 8);
                ulonglong2 x3 = *(const ulonglong2*)(ab + 12);
                unsigned long long acc = 0ULL;
                ffma2(acc, w0.x, x0.x); ffma2(acc, w0.y, x0.y);
                ffma2(acc, w1.x, x1.x); ffma2(acc, w1.y, x1.y);
                ffma2(acc, w2.x, x2.x); ffma2(acc, w2.y, x2.y);
                ffma2(acc, w3.x, x3.x); ffma2(acc, w3.y, x3.y);
                float s = unpack_add(acc);
                if (q) sm[M_PART + (q - 1) * 640 + n * 64 + c] = s;
                else   accs[n] = s;
            }
        }
        __syncthreads();
        if (q == 0) {
            float bias = __ldg(ba + s0 * D + c);
            #pragma unroll
            for (int n = 0; n < NC; n++) {
                float s = accs[n] + sm[M_PART + n * 64 + c]
                        + sm[M_PART + 640 + n * 64 + c]
                        + sm[M_PART + 1280 + n * 64 + c] + bias;
                sm[M_HS + n * 64 + c] = fmaxf(s, 0.f);
            }
        }
        cp_wait<2>();
        __syncthreads();                 // Wb(s0) ready; hs visible; bufA free

        if (s2 < 4096) issue(bufA, Wa + (size_t)s2 * 4096);
        cp_commit();

        // ---- stage 2: weights bufB, acts = hs ----
        {
            const float* wbase = sm + M_RING + bufB * 4352 + c * 68 + q * 16;
            ulonglong2 w0 = *(const ulonglong2*)(wbase);
            ulonglong2 w1 = *(const ulonglong2*)(wbase + 4);
            ulonglong2 w2 = *(const ulonglong2*)(wbase + 8);
            ulonglong2 w3 = *(const ulonglong2*)(wbase + 12);
            #pragma unroll
            for (int n = 0; n < NC; n++) {
                const float* ab = sm + M_HS + n * 64 + q * 16;
                ulonglong2 x0 = *(const ulonglong2*)(ab);
                ulonglong2 x1 = *(const ulonglong2*)(ab + 4);
                ulonglong2 x2 = *(const ulonglong2*)(ab + 8);
                ulonglong2 x3 = *(const ulonglong2*)(ab + 12);
                unsigned long long acc = 0ULL;
                ffma2(acc, w0.x, x0.x); ffma2(acc, w0.y, x0.y);
                ffma2(acc, w1.x, x1.x); ffma2(acc, w1.y, x1.y);
                ffma2(acc, w2.x, x2.x); ffma2(acc, w2.y, x2.y);
                ffma2(acc, w3.x, x3.x); ffma2(acc, w3.y, x3.y);
                float s = unpack_add(acc);
                if (q) sm[M_PART + (q - 1) * 640 + n * 64 + c] = s;
                else   accs[n] = s;
            }
        }
        __syncthreads();                 // bufB free; partials visible
        if (q == 0) {
            float bias = __ldg(bb + s0 * D + c);
            float m = -3.4e38f;
            #pragma unroll
            for (int n = 0; n < NC; n++) {
                float s = accs[n] + sm[M_PART + n * 64 + c]
                        + sm[M_PART + 640 + n * 64 + c]
                        + sm[M_PART + 1280 + n * 64 + c] + bias;
                m = fmaxf(m, s);
            }
            out[s0 * D + c] = m;
        }
        if (s2 < 4096) issue(bufB, Wb + (size_t)s2 * 4096);
        cp_commit();

        s0 = s1; s1 = s2; t++;
    }
}

// ---------------------------------------------------------------------------
extern "C" void kernel_launch(void* const* d_in, const int* in_sizes, int n_in,
                              void* d_out, int out_size)
{
    const float* cc0  = (const float*)d_in[0];
    const float* Wk   = (const float*)d_in[1];
    const float* bk   = (const float*)d_in[2];
    const float* Wq   = (const float*)d_in[3];
    const float* bq   = (const float*)d_in[4];
    const float* Wv   = (const float*)d_in[5];
    const float* bv   = (const float*)d_in[6];
    const float* cc_g = (const float*)d_in[7];
    const float* cc_b = (const float*)d_in[8];
    const float* W_ih = (const float*)d_in[9];
    const float* W_hh = (const float*)d_in[10];
    const float* b_ih = (const float*)d_in[11];
    const float* b_hh = (const float*)d_in[12];
    const float* ln_g = (const float*)d_in[13];
    const float* ln_b = (const float*)d_in[14];
    const float* W1   = (const float*)d_in[15];
    const float* b1   = (const float*)d_in[16];
    const float* W2   = (const float*)d_in[17];
    const float* b2   = (const float*)d_in[18];
    const float* Wa   = (const float*)d_in[19];
    const float* ba   = (const float*)d_in[20];
    const float* Wb   = (const float*)d_in[21];
    const float* bb   = (const float*)d_in[22];

    cudaFuncSetAttribute(slot_iter_kernel,
                         cudaFuncAttributeMaxDynamicSharedMemorySize, CORE_DYN_BYTES);
    cudaFuncSetAttribute(slot_mlp_kernel,
                         cudaFuncAttributeMaxDynamicSharedMemorySize, MLP_DYN_BYTES);

    reset_kernel<<<1, 1>>>();

    slot_iter_kernel<<<1, 640, CORE_DYN_BYTES>>>(
        cc0, Wk, bk, Wq, bq, Wv, bv, cc_g, cc_b,
        W_ih, W_hh, b_ih, b_hh, ln_g, ln_b, W1, b1, W2, b2);

    // MLP with programmatic dependent launch: overlaps the core's execution.
    cudaLaunchConfig_t cfg = {};
    cfg.gridDim = dim3(NBLK);
    cfg.blockDim = dim3(256);
    cfg.dynamicSmemBytes = MLP_DYN_BYTES;
    cfg.stream = 0;
    cudaLaunchAttribute attrs[1];
    attrs[0].id = cudaLaunchAttributeProgrammaticStreamSerialization;
    attrs[0].val.programmaticStreamSerializationAllowed = 1;
    cfg.attrs = attrs;
    cfg.numAttrs = 1;
    cudaLaunchKernelEx(&cfg, slot_mlp_kernel, Wa, ba, Wb, bb, (float*)d_out);
}